// round 9
// baseline (speedup 1.0000x reference)
#include <cuda_runtime.h>
#include <math.h>

// Problem constants
#define N_TOK 16384          // B*T
#define G     2
#define M     1024
#define D     256
#define GD    512            // G*D
#define GM    2048           // G*M

// Output layout (concatenated, float32):
//   quantized [8388608], code_perplexity [2], prob_perplexity [2],
//   quantization_inds [32768], commitment_loss [1]
#define OFF_Q    0
#define OFF_CODE 8388608
#define OFF_PROB 8388610
#define OFF_IND  8388612
#define OFF_LOSS 8421380

// -------- device scratch (static globals: no runtime allocation) --------
__device__ float  g_logits[33554432];   // [N_TOK, G, M] = 134 MB
__device__ float  g_sqe[GM];
__device__ float  g_avgprob[GM];
__device__ float  g_hardcnt[GM];
__device__ double g_commit;

// -------- packed f32x2 helpers (FFMA2: 2x fp32 FMA throughput) --------
__device__ __forceinline__ unsigned long long pk2(float lo, float hi) {
    unsigned long long r;
    asm("mov.b64 %0, {%1,%2};" : "=l"(r) : "f"(lo), "f"(hi));
    return r;
}
__device__ __forceinline__ void upk2(unsigned long long v, float& lo, float& hi) {
    asm("mov.b64 {%0,%1}, %2;" : "=f"(lo), "=f"(hi) : "l"(v));
}
__device__ __forceinline__ void fma2(unsigned long long& acc,
                                     unsigned long long a, unsigned long long b) {
    asm("fma.rn.f32x2 %0, %1, %2, %0;" : "+l"(acc) : "l"(a), "l"(b));
}

// ======================================================================
// K0: sq_e[g,m] = sum_d e^2 ; zero accumulators
// grid 256 blocks x 256 threads : one warp per (g,m) row
// ======================================================================
__global__ void k_prep(const float* __restrict__ emb) {
    int row  = blockIdx.x * 8 + (threadIdx.x >> 5);
    int lane = threadIdx.x & 31;
    if (row < GM) {
        const float* e = emb + (size_t)row * D;
        float s = 0.f;
        #pragma unroll
        for (int d = lane; d < D; d += 32) { float v = e[d]; s = fmaf(v, v, s); }
        #pragma unroll
        for (int o = 16; o > 0; o >>= 1) s += __shfl_xor_sync(0xffffffffu, s, o);
        if (lane == 0) {
            g_sqe[row]     = s;
            g_avgprob[row] = 0.f;
            g_hardcnt[row] = 0.f;
        }
    }
    if (blockIdx.x == 0 && threadIdx.x == 0) g_commit = 0.0;
}

// ======================================================================
// K1: L[n,g,m] = 2 * (x[n,g,:] . e[g,m,:]) - sq_e[g,m]
// fp32 tiled GEMM, 128x128 block tile, BK=16, 8x8 microtile, FFMA2
// grid (M/128, N/128, G) x 256 threads
// ======================================================================
#define BM 128
#define BN 128
#define BK 16

__global__ void __launch_bounds__(256) k_gemm(const float* __restrict__ x,
                                              const float* __restrict__ emb) {
    __shared__ float As[BK][BM];
    __shared__ float Bs[BK][BN];

    int g  = blockIdx.z;
    int m0 = blockIdx.x * BN;
    int n0 = blockIdx.y * BM;
    const float* A = x   + (size_t)g * D;        // row n: A[n*GD + d]
    const float* B = emb + (size_t)g * M * D;    // row m: B[m*D + d]

    int tid  = threadIdx.x;
    int tx   = tid & 15;          // 16 col-groups of 8
    int ty   = tid >> 4;          // 16 row-groups of 8
    int lrow = tid >> 2;          // 0..63
    int lcol = (tid & 3) << 2;    // 0,4,8,12

    unsigned long long acc[8][4];
    #pragma unroll
    for (int i = 0; i < 8; i++)
        #pragma unroll
        for (int j = 0; j < 4; j++) acc[i][j] = 0ULL;

    for (int k0 = 0; k0 < D; k0 += BK) {
        #pragma unroll
        for (int r = 0; r < 2; r++) {
            int row = lrow + r * 64;
            float4 va = *(const float4*)(A + (size_t)(n0 + row) * GD + k0 + lcol);
            As[lcol + 0][row] = va.x; As[lcol + 1][row] = va.y;
            As[lcol + 2][row] = va.z; As[lcol + 3][row] = va.w;
            float4 vb = *(const float4*)(B + (size_t)(m0 + row) * D + k0 + lcol);
            Bs[lcol + 0][row] = vb.x; Bs[lcol + 1][row] = vb.y;
            Bs[lcol + 2][row] = vb.z; Bs[lcol + 3][row] = vb.w;
        }
        __syncthreads();
        #pragma unroll
        for (int k = 0; k < BK; k++) {
            float4 a0 = *(const float4*)&As[k][ty * 8];
            float4 a1 = *(const float4*)&As[k][ty * 8 + 4];
            float4 b0 = *(const float4*)&Bs[k][tx * 8];
            float4 b1 = *(const float4*)&Bs[k][tx * 8 + 4];
            unsigned long long bb[4] = { pk2(b0.x, b0.y), pk2(b0.z, b0.w),
                                         pk2(b1.x, b1.y), pk2(b1.z, b1.w) };
            float av[8] = {a0.x, a0.y, a0.z, a0.w, a1.x, a1.y, a1.z, a1.w};
            #pragma unroll
            for (int i = 0; i < 8; i++) {
                unsigned long long aa = pk2(av[i], av[i]);
                #pragma unroll
                for (int j = 0; j < 4; j++) fma2(acc[i][j], aa, bb[j]);
            }
        }
        __syncthreads();
    }

    // epilogue: L = 2*cross - sq_e
    float sq[8];
    #pragma unroll
    for (int j = 0; j < 8; j++) sq[j] = g_sqe[g * M + m0 + tx * 8 + j];
    #pragma unroll
    for (int i = 0; i < 8; i++) {
        int n = n0 + ty * 8 + i;
        float* Lrow = g_logits + ((size_t)n * G + g) * M + m0 + tx * 8;
        #pragma unroll
        for (int j = 0; j < 4; j++) {
            float f0, f1; upk2(acc[i][j], f0, f1);
            float2 o;
            o.x = 2.0f * f0 - sq[2 * j];
            o.y = 2.0f * f1 - sq[2 * j + 1];
            *(float2*)(Lrow + 2 * j) = o;
        }
    }
}

// ======================================================================
// K2: per-row fused epilogue. 16 rows per block, 256 threads.
//  - hard argmax (first-occurrence ties)     -> hard counts
//  - gumbel argmax of L + (-log(-log(u)))    -> inds, gather, commit loss
//  - softmax over row                        -> avg_probs accumulation
// grid (N/16, G) x 256
// ======================================================================
#define ROWS 16

__global__ void __launch_bounds__(256) k_rows(const float* __restrict__ x,
                                              const float* __restrict__ emb,
                                              const float* __restrict__ gu,
                                              float* __restrict__ out) {
    int g    = blockIdx.y;
    int n0   = blockIdx.x * ROWS;
    int tid  = threadIdx.x;
    int lane = tid & 31, wid = tid >> 5;

    __shared__ float svL[8]; __shared__ int siL[8];
    __shared__ float svG[8]; __shared__ int siG[8];
    __shared__ float sLmax;  __shared__ int sLidx; __shared__ int sGidx;
    __shared__ float sZ;

    float accP[4]  = {0.f, 0.f, 0.f, 0.f};
    float hardC[4] = {0.f, 0.f, 0.f, 0.f};
    float commitLocal = 0.f;

    for (int r = 0; r < ROWS; r++) {
        int n = n0 + r;
        const float* Lrow = g_logits + ((size_t)n * G + g) * M;
        const float* Urow = gu       + ((size_t)n * G + g) * M;

        float Lv[4];
        float lmax = -3.4e38f; int lIdx = 0;
        float gmax = -3.4e38f; int gIdx = 0;
        #pragma unroll
        for (int j = 0; j < 4; j++) {
            int m   = tid + j * 256;            // ascending m within thread
            float L = Lrow[m];
            float u = Urow[m];
            // precise logf: -log(u) can be ~1e-6 when u -> 1; __logf would
            // destroy relative accuracy and flip argmaxes
            float noise = -logf(-logf(u));
            float gv = L + noise;
            Lv[j] = L;
            if (L  > lmax) { lmax = L;  lIdx = m; }   // strict > keeps first
            if (gv > gmax) { gmax = gv; gIdx = m; }
        }
        // warp argmax reductions (tie-break: smaller index)
        #pragma unroll
        for (int o = 16; o > 0; o >>= 1) {
            float v2 = __shfl_xor_sync(0xffffffffu, lmax, o);
            int   i2 = __shfl_xor_sync(0xffffffffu, lIdx, o);
            if (v2 > lmax || (v2 == lmax && i2 < lIdx)) { lmax = v2; lIdx = i2; }
            float v3 = __shfl_xor_sync(0xffffffffu, gmax, o);
            int   i3 = __shfl_xor_sync(0xffffffffu, gIdx, o);
            if (v3 > gmax || (v3 == gmax && i3 < gIdx)) { gmax = v3; gIdx = i3; }
        }
        if (lane == 0) { svL[wid] = lmax; siL[wid] = lIdx;
                         svG[wid] = gmax; siG[wid] = gIdx; }
        __syncthreads();
        if (tid == 0) {
            float lm = svL[0]; int li = siL[0];
            float gm = svG[0]; int gi = siG[0];
            #pragma unroll
            for (int w = 1; w < 8; w++) {
                if (svL[w] > lm || (svL[w] == lm && siL[w] < li)) { lm = svL[w]; li = siL[w]; }
                if (svG[w] > gm || (svG[w] == gm && siG[w] < gi)) { gm = svG[w]; gi = siG[w]; }
            }
            sLmax = lm; sLidx = li; sGidx = gi;
        }
        __syncthreads();
        float rowMax = sLmax;
        int   hIdx   = sLidx;
        int   qIdx   = sGidx;

        // softmax partition sum
        float e[4];
        float ez = 0.f;
        #pragma unroll
        for (int j = 0; j < 4; j++) { e[j] = __expf(Lv[j] - rowMax); ez += e[j]; }
        #pragma unroll
        for (int o = 16; o > 0; o >>= 1) ez += __shfl_xor_sync(0xffffffffu, ez, o);
        if (lane == 0) svL[wid] = ez;
        __syncthreads();
        if (tid == 0) {
            float z = 0.f;
            #pragma unroll
            for (int w = 0; w < 8; w++) z += svL[w];
            sZ = z;
        }
        __syncthreads();
        float invZ = 1.0f / sZ;
        #pragma unroll
        for (int j = 0; j < 4; j++) accP[j] += e[j] * invZ;

        // hard-assignment count (owner thread of hIdx)
        if (tid == (hIdx & 255)) hardC[hIdx >> 8] += 1.0f;

        // gumbel index output + gather + commitment partial
        if (tid == 0) out[OFF_IND + n * G + g] = (float)qIdx;
        const float* er = emb + ((size_t)g * M + qIdx) * D;
        float q  = er[tid];
        size_t xo = (size_t)n * GD + (size_t)g * D + tid;
        out[OFF_Q + xo] = q;
        float dd = x[xo] - q;
        commitLocal = fmaf(dd, dd, commitLocal);
    }

    // flush per-block accumulators (2M atomics total vs 33.5M naive)
    #pragma unroll
    for (int j = 0; j < 4; j++) {
        atomicAdd(&g_avgprob[g * M + tid + j * 256], accP[j]);
        if (hardC[j] != 0.f) atomicAdd(&g_hardcnt[g * M + tid + j * 256], hardC[j]);
    }
    // commitment loss block reduce
    #pragma unroll
    for (int o = 16; o > 0; o >>= 1)
        commitLocal += __shfl_xor_sync(0xffffffffu, commitLocal, o);
    __syncthreads();
    if (lane == 0) svL[wid] = commitLocal;
    __syncthreads();
    if (tid == 0) {
        float s = 0.f;
        #pragma unroll
        for (int w = 0; w < 8; w++) s += svL[w];
        atomicAdd(&g_commit, (double)s);
    }
}

// ======================================================================
// K3: perplexities + loss. grid (G) x 256
// ======================================================================
__global__ void k_final(float* __restrict__ out) {
    int g = blockIdx.x;
    int tid = threadIdx.x;
    __shared__ float s1[8], s2[8];
    float c = 0.f, p = 0.f;
    for (int m = tid; m < M; m += 256) {
        float hp = g_hardcnt[g * M + m] * (1.0f / N_TOK);
        float ap = g_avgprob[g * M + m] * (1.0f / N_TOK);
        c -= hp * log2f(hp + 1e-10f);
        p -= ap * log2f(ap + 1e-10f);
    }
    #pragma unroll
    for (int o = 16; o > 0; o >>= 1) {
        c += __shfl_xor_sync(0xffffffffu, c, o);
        p += __shfl_xor_sync(0xffffffffu, p, o);
    }
    int lane = tid & 31, w = tid >> 5;
    if (lane == 0) { s1[w] = c; s2[w] = p; }
    __syncthreads();
    if (tid == 0) {
        float cc = 0.f, pp = 0.f;
        #pragma unroll
        for (int i = 0; i < 8; i++) { cc += s1[i]; pp += s2[i]; }
        out[OFF_CODE + g] = cc;
        out[OFF_PROB + g] = pp;
        if (g == 0) out[OFF_LOSS] = (float)(g_commit / 8388608.0);  // mean over B*T*G*D
    }
}

// ======================================================================
extern "C" void kernel_launch(void* const* d_in, const int* in_sizes, int n_in,
                              void* d_out, int out_size) {
    const float* x   = (const float*)d_in[0];   // [B,T,G*D]
    const float* emb = (const float*)d_in[1];   // [G,M,D]
    const float* gu  = (const float*)d_in[2];   // [N,G,M]
    float* out = (float*)d_out;

    k_prep <<<256, 256>>>(emb);
    k_gemm <<<dim3(M / BN, N_TOK / BM, G), 256>>>(x, emb);
    k_rows <<<dim3(N_TOK / ROWS, G), 256>>>(x, emb, gu, out);
    k_final<<<G, 256>>>(out);
}

// round 10
// speedup vs baseline: 1.0495x; 1.0495x over previous
#include <cuda_runtime.h>
#include <math.h>

// Problem constants
#define N_TOK 16384          // B*T
#define G     2
#define M     1024
#define D     256
#define GD    512            // G*D
#define GM    2048           // G*M

// Output layout (concatenated, float32):
//   quantized [8388608], code_perplexity [2], prob_perplexity [2],
//   quantization_inds [32768], commitment_loss [1]
#define OFF_Q    0
#define OFF_CODE 8388608
#define OFF_PROB 8388610
#define OFF_IND  8388612
#define OFF_LOSS 8421380

// -------- device scratch (static globals: no runtime allocation) --------
__device__ float  g_logits[33554432];   // [N_TOK, G, M] = 134 MB
__device__ float  g_sqe[GM];
__device__ float  g_avgprob[GM];
__device__ float  g_hardcnt[GM];
__device__ double g_commit;

// -------- packed f32x2 helpers (FFMA2: 2x fp32 FMA throughput) --------
__device__ __forceinline__ unsigned long long pk2(float lo, float hi) {
    unsigned long long r;
    asm("mov.b64 %0, {%1,%2};" : "=l"(r) : "f"(lo), "f"(hi));
    return r;
}
__device__ __forceinline__ void upk2(unsigned long long v, float& lo, float& hi) {
    asm("mov.b64 {%0,%1}, %2;" : "=f"(lo), "=f"(hi) : "l"(v));
}
__device__ __forceinline__ void fma2(unsigned long long& acc,
                                     unsigned long long a, unsigned long long b) {
    asm("fma.rn.f32x2 %0, %1, %2, %0;" : "+l"(acc) : "l"(a), "l"(b));
}

// ======================================================================
// K0: sq_e[g,m] = sum_d e^2 ; zero accumulators
// grid 256 blocks x 256 threads : one warp per (g,m) row
// ======================================================================
__global__ void k_prep(const float* __restrict__ emb) {
    int row  = blockIdx.x * 8 + (threadIdx.x >> 5);
    int lane = threadIdx.x & 31;
    if (row < GM) {
        const float* e = emb + (size_t)row * D;
        float s = 0.f;
        #pragma unroll
        for (int d = lane; d < D; d += 32) { float v = e[d]; s = fmaf(v, v, s); }
        #pragma unroll
        for (int o = 16; o > 0; o >>= 1) s += __shfl_xor_sync(0xffffffffu, s, o);
        if (lane == 0) {
            g_sqe[row]     = s;
            g_avgprob[row] = 0.f;
            g_hardcnt[row] = 0.f;
        }
    }
    if (blockIdx.x == 0 && threadIdx.x == 0) g_commit = 0.0;
}

// ======================================================================
// K1: L[n,g,m] = 2 * (x[n,g,:] . e[g,m,:]) - sq_e[g,m]
// fp32 tiled GEMM, 128x128 block tile, BK=16, 8x8 microtile, FFMA2
// grid (M/128, N/128, G) x 256 threads
// ======================================================================
#define BM 128
#define BN 128
#define BK 16

__global__ void __launch_bounds__(256) k_gemm(const float* __restrict__ x,
                                              const float* __restrict__ emb) {
    __shared__ float As[BK][BM];
    __shared__ float Bs[BK][BN];

    int g  = blockIdx.z;
    int m0 = blockIdx.x * BN;
    int n0 = blockIdx.y * BM;
    const float* A = x   + (size_t)g * D;        // row n: A[n*GD + d]
    const float* B = emb + (size_t)g * M * D;    // row m: B[m*D + d]

    int tid  = threadIdx.x;
    int tx   = tid & 15;          // 16 col-groups of 8
    int ty   = tid >> 4;          // 16 row-groups of 8
    int lrow = tid >> 2;          // 0..63
    int lcol = (tid & 3) << 2;    // 0,4,8,12

    unsigned long long acc[8][4];
    #pragma unroll
    for (int i = 0; i < 8; i++)
        #pragma unroll
        for (int j = 0; j < 4; j++) acc[i][j] = 0ULL;

    for (int k0 = 0; k0 < D; k0 += BK) {
        #pragma unroll
        for (int r = 0; r < 2; r++) {
            int row = lrow + r * 64;
            float4 va = *(const float4*)(A + (size_t)(n0 + row) * GD + k0 + lcol);
            As[lcol + 0][row] = va.x; As[lcol + 1][row] = va.y;
            As[lcol + 2][row] = va.z; As[lcol + 3][row] = va.w;
            float4 vb = *(const float4*)(B + (size_t)(m0 + row) * D + k0 + lcol);
            Bs[lcol + 0][row] = vb.x; Bs[lcol + 1][row] = vb.y;
            Bs[lcol + 2][row] = vb.z; Bs[lcol + 3][row] = vb.w;
        }
        __syncthreads();
        #pragma unroll
        for (int k = 0; k < BK; k++) {
            float4 a0 = *(const float4*)&As[k][ty * 8];
            float4 a1 = *(const float4*)&As[k][ty * 8 + 4];
            float4 b0 = *(const float4*)&Bs[k][tx * 8];
            float4 b1 = *(const float4*)&Bs[k][tx * 8 + 4];
            unsigned long long bb[4] = { pk2(b0.x, b0.y), pk2(b0.z, b0.w),
                                         pk2(b1.x, b1.y), pk2(b1.z, b1.w) };
            float av[8] = {a0.x, a0.y, a0.z, a0.w, a1.x, a1.y, a1.z, a1.w};
            #pragma unroll
            for (int i = 0; i < 8; i++) {
                unsigned long long aa = pk2(av[i], av[i]);
                #pragma unroll
                for (int j = 0; j < 4; j++) fma2(acc[i][j], aa, bb[j]);
            }
        }
        __syncthreads();
    }

    // epilogue: L = 2*cross - sq_e
    float sq[8];
    #pragma unroll
    for (int j = 0; j < 8; j++) sq[j] = g_sqe[g * M + m0 + tx * 8 + j];
    #pragma unroll
    for (int i = 0; i < 8; i++) {
        int n = n0 + ty * 8 + i;
        float* Lrow = g_logits + ((size_t)n * G + g) * M + m0 + tx * 8;
        #pragma unroll
        for (int j = 0; j < 4; j++) {
            float f0, f1; upk2(acc[i][j], f0, f1);
            float2 o;
            o.x = 2.0f * f0 - sq[2 * j];
            o.y = 2.0f * f1 - sq[2 * j + 1];
            *(float2*)(Lrow + 2 * j) = o;
        }
    }
}

// ======================================================================
// K2: per-row fused epilogue. 16 rows per block, 256 threads.
//  - hard argmax (first-occurrence ties)     -> hard counts
//  - gumbel argmax of L + (-log(-log(u)))    -> inds, gather, commit loss
//  - softmax over row                        -> avg_probs accumulation
// grid (N/16, G) x 256
// ======================================================================
#define ROWS 16

__global__ void __launch_bounds__(256) k_rows(const float* __restrict__ x,
                                              const float* __restrict__ emb,
                                              const float* __restrict__ gu,
                                              float* __restrict__ out) {
    int g    = blockIdx.y;
    int n0   = blockIdx.x * ROWS;
    int tid  = threadIdx.x;
    int lane = tid & 31, wid = tid >> 5;

    __shared__ float svL[8]; __shared__ int siL[8];
    __shared__ float svG[8]; __shared__ int siG[8];
    __shared__ float sLmax;  __shared__ int sLidx; __shared__ int sGidx;
    __shared__ float sZ;

    float accP[4]  = {0.f, 0.f, 0.f, 0.f};
    float hardC[4] = {0.f, 0.f, 0.f, 0.f};
    float commitLocal = 0.f;

    for (int r = 0; r < ROWS; r++) {
        int n = n0 + r;
        const float* Lrow = g_logits + ((size_t)n * G + g) * M;
        const float* Urow = gu       + ((size_t)n * G + g) * M;

        float Lv[4];
        float lmax = -3.4e38f; int lIdx = 0;
        float gmax = -3.4e38f; int gIdx = 0;
        #pragma unroll
        for (int j = 0; j < 4; j++) {
            int m   = tid + j * 256;            // ascending m within thread
            float L = Lrow[m];
            float u = Urow[m];
            // precise logf: -log(u) can be ~1e-6 when u -> 1; __logf would
            // destroy relative accuracy and flip argmaxes
            float noise = -logf(-logf(u));
            float gv = L + noise;
            Lv[j] = L;
            if (L  > lmax) { lmax = L;  lIdx = m; }   // strict > keeps first
            if (gv > gmax) { gmax = gv; gIdx = m; }
        }
        // warp argmax reductions (tie-break: smaller index)
        #pragma unroll
        for (int o = 16; o > 0; o >>= 1) {
            float v2 = __shfl_xor_sync(0xffffffffu, lmax, o);
            int   i2 = __shfl_xor_sync(0xffffffffu, lIdx, o);
            if (v2 > lmax || (v2 == lmax && i2 < lIdx)) { lmax = v2; lIdx = i2; }
            float v3 = __shfl_xor_sync(0xffffffffu, gmax, o);
            int   i3 = __shfl_xor_sync(0xffffffffu, gIdx, o);
            if (v3 > gmax || (v3 == gmax && i3 < gIdx)) { gmax = v3; gIdx = i3; }
        }
        if (lane == 0) { svL[wid] = lmax; siL[wid] = lIdx;
                         svG[wid] = gmax; siG[wid] = gIdx; }
        __syncthreads();
        if (tid == 0) {
            float lm = svL[0]; int li = siL[0];
            float gm = svG[0]; int gi = siG[0];
            #pragma unroll
            for (int w = 1; w < 8; w++) {
                if (svL[w] > lm || (svL[w] == lm && siL[w] < li)) { lm = svL[w]; li = siL[w]; }
                if (svG[w] > gm || (svG[w] == gm && siG[w] < gi)) { gm = svG[w]; gi = siG[w]; }
            }
            sLmax = lm; sLidx = li; sGidx = gi;
        }
        __syncthreads();
        float rowMax = sLmax;
        int   hIdx   = sLidx;
        int   qIdx   = sGidx;

        // softmax partition sum
        float e[4];
        float ez = 0.f;
        #pragma unroll
        for (int j = 0; j < 4; j++) { e[j] = __expf(Lv[j] - rowMax); ez += e[j]; }
        #pragma unroll
        for (int o = 16; o > 0; o >>= 1) ez += __shfl_xor_sync(0xffffffffu, ez, o);
        if (lane == 0) svL[wid] = ez;
        __syncthreads();
        if (tid == 0) {
            float z = 0.f;
            #pragma unroll
            for (int w = 0; w < 8; w++) z += svL[w];
            sZ = z;
        }
        __syncthreads();
        float invZ = 1.0f / sZ;
        #pragma unroll
        for (int j = 0; j < 4; j++) accP[j] += e[j] * invZ;

        // hard-assignment count (owner thread of hIdx)
        if (tid == (hIdx & 255)) hardC[hIdx >> 8] += 1.0f;

        // gumbel index output + gather + commitment partial
        if (tid == 0) out[OFF_IND + n * G + g] = (float)qIdx;
        const float* er = emb + ((size_t)g * M + qIdx) * D;
        float q  = er[tid];
        size_t xo = (size_t)n * GD + (size_t)g * D + tid;
        out[OFF_Q + xo] = q;
        float dd = x[xo] - q;
        commitLocal = fmaf(dd, dd, commitLocal);
    }

    // flush per-block accumulators (2M atomics total vs 33.5M naive)
    #pragma unroll
    for (int j = 0; j < 4; j++) {
        atomicAdd(&g_avgprob[g * M + tid + j * 256], accP[j]);
        if (hardC[j] != 0.f) atomicAdd(&g_hardcnt[g * M + tid + j * 256], hardC[j]);
    }
    // commitment loss block reduce
    #pragma unroll
    for (int o = 16; o > 0; o >>= 1)
        commitLocal += __shfl_xor_sync(0xffffffffu, commitLocal, o);
    __syncthreads();
    if (lane == 0) svL[wid] = commitLocal;
    __syncthreads();
    if (tid == 0) {
        float s = 0.f;
        #pragma unroll
        for (int w = 0; w < 8; w++) s += svL[w];
        atomicAdd(&g_commit, (double)s);
    }
}

// ======================================================================
// K3: perplexities + loss. grid (G) x 256
// ======================================================================
__global__ void k_final(float* __restrict__ out) {
    int g = blockIdx.x;
    int tid = threadIdx.x;
    __shared__ float s1[8], s2[8];
    float c = 0.f, p = 0.f;
    for (int m = tid; m < M; m += 256) {
        float hp = g_hardcnt[g * M + m] * (1.0f / N_TOK);
        float ap = g_avgprob[g * M + m] * (1.0f / N_TOK);
        c -= hp * log2f(hp + 1e-10f);
        p -= ap * log2f(ap + 1e-10f);
    }
    #pragma unroll
    for (int o = 16; o > 0; o >>= 1) {
        c += __shfl_xor_sync(0xffffffffu, c, o);
        p += __shfl_xor_sync(0xffffffffu, p, o);
    }
    int lane = tid & 31, w = tid >> 5;
    if (lane == 0) { s1[w] = c; s2[w] = p; }
    __syncthreads();
    if (tid == 0) {
        float cc = 0.f, pp = 0.f;
        #pragma unroll
        for (int i = 0; i < 8; i++) { cc += s1[i]; pp += s2[i]; }
        out[OFF_CODE + g] = cc;
        out[OFF_PROB + g] = pp;
        if (g == 0) out[OFF_LOSS] = (float)(g_commit / 8388608.0);  // mean over B*T*G*D
    }
}

// ======================================================================
extern "C" void kernel_launch(void* const* d_in, const int* in_sizes, int n_in,
                              void* d_out, int out_size) {
    const float* x   = (const float*)d_in[0];   // [B,T,G*D]
    const float* emb = (const float*)d_in[1];   // [G,M,D]
    const float* gu  = (const float*)d_in[2];   // [N,G,M]
    float* out = (float*)d_out;

    k_prep <<<256, 256>>>(emb);
    k_gemm <<<dim3(M / BN, N_TOK / BM, G), 256>>>(x, emb);
    k_rows <<<dim3(N_TOK / ROWS, G), 256>>>(x, emb, gu, out);
    k_final<<<G, 256>>>(out);
}

// round 11
// speedup vs baseline: 1.0530x; 1.0033x over previous
#include <cuda_runtime.h>
#include <math.h>

// Problem constants
#define N_TOK 16384          // B*T
#define G     2
#define M     1024
#define D     256
#define GD    512            // G*D
#define GM    2048           // G*M

// Output layout (concatenated, float32):
//   quantized [8388608], code_perplexity [2], prob_perplexity [2],
//   quantization_inds [32768], commitment_loss [1]
#define OFF_Q    0
#define OFF_CODE 8388608
#define OFF_PROB 8388610
#define OFF_IND  8388612
#define OFF_LOSS 8421380

// -------- device scratch (static globals: no runtime allocation) --------
__device__ float  g_logits[33554432];   // [N_TOK, G, M] = 134 MB
__device__ float  g_sqe[GM];
__device__ float  g_avgprob[GM];
__device__ float  g_hardcnt[GM];
__device__ double g_commit;

// -------- packed f32x2 helpers (FFMA2: 2x fp32 FMA throughput) --------
__device__ __forceinline__ unsigned long long pk2(float lo, float hi) {
    unsigned long long r;
    asm("mov.b64 %0, {%1,%2};" : "=l"(r) : "f"(lo), "f"(hi));
    return r;
}
__device__ __forceinline__ void upk2(unsigned long long v, float& lo, float& hi) {
    asm("mov.b64 {%0,%1}, %2;" : "=f"(lo), "=f"(hi) : "l"(v));
}
__device__ __forceinline__ void fma2(unsigned long long& acc,
                                     unsigned long long a, unsigned long long b) {
    asm("fma.rn.f32x2 %0, %1, %2, %0;" : "+l"(acc) : "l"(a), "l"(b));
}

// ======================================================================
// K0: sq_e[g,m] = sum_d e^2 ; zero accumulators
// grid 256 blocks x 256 threads : one warp per (g,m) row
// ======================================================================
__global__ void k_prep(const float* __restrict__ emb) {
    int row  = blockIdx.x * 8 + (threadIdx.x >> 5);
    int lane = threadIdx.x & 31;
    if (row < GM) {
        const float* e = emb + (size_t)row * D;
        float s = 0.f;
        #pragma unroll
        for (int d = lane; d < D; d += 32) { float v = e[d]; s = fmaf(v, v, s); }
        #pragma unroll
        for (int o = 16; o > 0; o >>= 1) s += __shfl_xor_sync(0xffffffffu, s, o);
        if (lane == 0) {
            g_sqe[row]     = s;
            g_avgprob[row] = 0.f;
            g_hardcnt[row] = 0.f;
        }
    }
    if (blockIdx.x == 0 && threadIdx.x == 0) g_commit = 0.0;
}

// ======================================================================
// K1: L[n,g,m] = 2 * (x[n,g,:] . e[g,m,:]) - sq_e[g,m]
// fp32 tiled GEMM, 128x128 block tile, BK=16, 8x8 microtile, FFMA2
// grid (M/128, N/128, G) x 256 threads
// ======================================================================
#define BM 128
#define BN 128
#define BK 16

__global__ void __launch_bounds__(256) k_gemm(const float* __restrict__ x,
                                              const float* __restrict__ emb) {
    __shared__ float As[BK][BM];
    __shared__ float Bs[BK][BN];

    int g  = blockIdx.z;
    int m0 = blockIdx.x * BN;
    int n0 = blockIdx.y * BM;
    const float* A = x   + (size_t)g * D;        // row n: A[n*GD + d]
    const float* B = emb + (size_t)g * M * D;    // row m: B[m*D + d]

    int tid  = threadIdx.x;
    int tx   = tid & 15;          // 16 col-groups of 8
    int ty   = tid >> 4;          // 16 row-groups of 8
    int lrow = tid >> 2;          // 0..63
    int lcol = (tid & 3) << 2;    // 0,4,8,12

    unsigned long long acc[8][4];
    #pragma unroll
    for (int i = 0; i < 8; i++)
        #pragma unroll
        for (int j = 0; j < 4; j++) acc[i][j] = 0ULL;

    for (int k0 = 0; k0 < D; k0 += BK) {
        #pragma unroll
        for (int r = 0; r < 2; r++) {
            int row = lrow + r * 64;
            float4 va = *(const float4*)(A + (size_t)(n0 + row) * GD + k0 + lcol);
            As[lcol + 0][row] = va.x; As[lcol + 1][row] = va.y;
            As[lcol + 2][row] = va.z; As[lcol + 3][row] = va.w;
            float4 vb = *(const float4*)(B + (size_t)(m0 + row) * D + k0 + lcol);
            Bs[lcol + 0][row] = vb.x; Bs[lcol + 1][row] = vb.y;
            Bs[lcol + 2][row] = vb.z; Bs[lcol + 3][row] = vb.w;
        }
        __syncthreads();
        #pragma unroll
        for (int k = 0; k < BK; k++) {
            float4 a0 = *(const float4*)&As[k][ty * 8];
            float4 a1 = *(const float4*)&As[k][ty * 8 + 4];
            float4 b0 = *(const float4*)&Bs[k][tx * 8];
            float4 b1 = *(const float4*)&Bs[k][tx * 8 + 4];
            unsigned long long bb[4] = { pk2(b0.x, b0.y), pk2(b0.z, b0.w),
                                         pk2(b1.x, b1.y), pk2(b1.z, b1.w) };
            float av[8] = {a0.x, a0.y, a0.z, a0.w, a1.x, a1.y, a1.z, a1.w};
            #pragma unroll
            for (int i = 0; i < 8; i++) {
                unsigned long long aa = pk2(av[i], av[i]);
                #pragma unroll
                for (int j = 0; j < 4; j++) fma2(acc[i][j], aa, bb[j]);
            }
        }
        __syncthreads();
    }

    // epilogue: L = 2*cross - sq_e
    float sq[8];
    #pragma unroll
    for (int j = 0; j < 8; j++) sq[j] = g_sqe[g * M + m0 + tx * 8 + j];
    #pragma unroll
    for (int i = 0; i < 8; i++) {
        int n = n0 + ty * 8 + i;
        float* Lrow = g_logits + ((size_t)n * G + g) * M + m0 + tx * 8;
        #pragma unroll
        for (int j = 0; j < 4; j++) {
            float f0, f1; upk2(acc[i][j], f0, f1);
            float2 o;
            o.x = 2.0f * f0 - sq[2 * j];
            o.y = 2.0f * f1 - sq[2 * j + 1];
            *(float2*)(Lrow + 2 * j) = o;
        }
    }
}

// ======================================================================
// K2: per-row fused epilogue. 16 rows per block, 256 threads.
//  - hard argmax (first-occurrence ties)     -> hard counts
//  - gumbel argmax of L + (-log(-log(u)))    -> inds, gather, commit loss
//  - softmax over row                        -> avg_probs accumulation
// grid (N/16, G) x 256
// ======================================================================
#define ROWS 16

__global__ void __launch_bounds__(256) k_rows(const float* __restrict__ x,
                                              const float* __restrict__ emb,
                                              const float* __restrict__ gu,
                                              float* __restrict__ out) {
    int g    = blockIdx.y;
    int n0   = blockIdx.x * ROWS;
    int tid  = threadIdx.x;
    int lane = tid & 31, wid = tid >> 5;

    __shared__ float svL[8]; __shared__ int siL[8];
    __shared__ float svG[8]; __shared__ int siG[8];
    __shared__ float sLmax;  __shared__ int sLidx; __shared__ int sGidx;
    __shared__ float sZ;

    float accP[4]  = {0.f, 0.f, 0.f, 0.f};
    float hardC[4] = {0.f, 0.f, 0.f, 0.f};
    float commitLocal = 0.f;

    for (int r = 0; r < ROWS; r++) {
        int n = n0 + r;
        const float* Lrow = g_logits + ((size_t)n * G + g) * M;
        const float* Urow = gu       + ((size_t)n * G + g) * M;

        float Lv[4];
        float lmax = -3.4e38f; int lIdx = 0;
        float gmax = -3.4e38f; int gIdx = 0;
        #pragma unroll
        for (int j = 0; j < 4; j++) {
            int m   = tid + j * 256;            // ascending m within thread
            float L = Lrow[m];
            float u = Urow[m];
            // precise logf: -log(u) can be ~1e-6 when u -> 1; __logf would
            // destroy relative accuracy and flip argmaxes
            float noise = -logf(-logf(u));
            float gv = L + noise;
            Lv[j] = L;
            if (L  > lmax) { lmax = L;  lIdx = m; }   // strict > keeps first
            if (gv > gmax) { gmax = gv; gIdx = m; }
        }
        // warp argmax reductions (tie-break: smaller index)
        #pragma unroll
        for (int o = 16; o > 0; o >>= 1) {
            float v2 = __shfl_xor_sync(0xffffffffu, lmax, o);
            int   i2 = __shfl_xor_sync(0xffffffffu, lIdx, o);
            if (v2 > lmax || (v2 == lmax && i2 < lIdx)) { lmax = v2; lIdx = i2; }
            float v3 = __shfl_xor_sync(0xffffffffu, gmax, o);
            int   i3 = __shfl_xor_sync(0xffffffffu, gIdx, o);
            if (v3 > gmax || (v3 == gmax && i3 < gIdx)) { gmax = v3; gIdx = i3; }
        }
        if (lane == 0) { svL[wid] = lmax; siL[wid] = lIdx;
                         svG[wid] = gmax; siG[wid] = gIdx; }
        __syncthreads();
        if (tid == 0) {
            float lm = svL[0]; int li = siL[0];
            float gm = svG[0]; int gi = siG[0];
            #pragma unroll
            for (int w = 1; w < 8; w++) {
                if (svL[w] > lm || (svL[w] == lm && siL[w] < li)) { lm = svL[w]; li = siL[w]; }
                if (svG[w] > gm || (svG[w] == gm && siG[w] < gi)) { gm = svG[w]; gi = siG[w]; }
            }
            sLmax = lm; sLidx = li; sGidx = gi;
        }
        __syncthreads();
        float rowMax = sLmax;
        int   hIdx   = sLidx;
        int   qIdx   = sGidx;

        // softmax partition sum
        float e[4];
        float ez = 0.f;
        #pragma unroll
        for (int j = 0; j < 4; j++) { e[j] = __expf(Lv[j] - rowMax); ez += e[j]; }
        #pragma unroll
        for (int o = 16; o > 0; o >>= 1) ez += __shfl_xor_sync(0xffffffffu, ez, o);
        if (lane == 0) svL[wid] = ez;
        __syncthreads();
        if (tid == 0) {
            float z = 0.f;
            #pragma unroll
            for (int w = 0; w < 8; w++) z += svL[w];
            sZ = z;
        }
        __syncthreads();
        float invZ = 1.0f / sZ;
        #pragma unroll
        for (int j = 0; j < 4; j++) accP[j] += e[j] * invZ;

        // hard-assignment count (owner thread of hIdx)
        if (tid == (hIdx & 255)) hardC[hIdx >> 8] += 1.0f;

        // gumbel index output + gather + commitment partial
        if (tid == 0) out[OFF_IND + n * G + g] = (float)qIdx;
        const float* er = emb + ((size_t)g * M + qIdx) * D;
        float q  = er[tid];
        size_t xo = (size_t)n * GD + (size_t)g * D + tid;
        out[OFF_Q + xo] = q;
        float dd = x[xo] - q;
        commitLocal = fmaf(dd, dd, commitLocal);
    }

    // flush per-block accumulators (2M atomics total vs 33.5M naive)
    #pragma unroll
    for (int j = 0; j < 4; j++) {
        atomicAdd(&g_avgprob[g * M + tid + j * 256], accP[j]);
        if (hardC[j] != 0.f) atomicAdd(&g_hardcnt[g * M + tid + j * 256], hardC[j]);
    }
    // commitment loss block reduce
    #pragma unroll
    for (int o = 16; o > 0; o >>= 1)
        commitLocal += __shfl_xor_sync(0xffffffffu, commitLocal, o);
    __syncthreads();
    if (lane == 0) svL[wid] = commitLocal;
    __syncthreads();
    if (tid == 0) {
        float s = 0.f;
        #pragma unroll
        for (int w = 0; w < 8; w++) s += svL[w];
        atomicAdd(&g_commit, (double)s);
    }
}

// ======================================================================
// K3: perplexities + loss. grid (G) x 256
// ======================================================================
__global__ void k_final(float* __restrict__ out) {
    int g = blockIdx.x;
    int tid = threadIdx.x;
    __shared__ float s1[8], s2[8];
    float c = 0.f, p = 0.f;
    for (int m = tid; m < M; m += 256) {
        float hp = g_hardcnt[g * M + m] * (1.0f / N_TOK);
        float ap = g_avgprob[g * M + m] * (1.0f / N_TOK);
        c -= hp * log2f(hp + 1e-10f);
        p -= ap * log2f(ap + 1e-10f);
    }
    #pragma unroll
    for (int o = 16; o > 0; o >>= 1) {
        c += __shfl_xor_sync(0xffffffffu, c, o);
        p += __shfl_xor_sync(0xffffffffu, p, o);
    }
    int lane = tid & 31, w = tid >> 5;
    if (lane == 0) { s1[w] = c; s2[w] = p; }
    __syncthreads();
    if (tid == 0) {
        float cc = 0.f, pp = 0.f;
        #pragma unroll
        for (int i = 0; i < 8; i++) { cc += s1[i]; pp += s2[i]; }
        out[OFF_CODE + g] = cc;
        out[OFF_PROB + g] = pp;
        if (g == 0) out[OFF_LOSS] = (float)(g_commit / 8388608.0);  // mean over B*T*G*D
    }
}

// ======================================================================
extern "C" void kernel_launch(void* const* d_in, const int* in_sizes, int n_in,
                              void* d_out, int out_size) {
    const float* x   = (const float*)d_in[0];   // [B,T,G*D]
    const float* emb = (const float*)d_in[1];   // [G,M,D]
    const float* gu  = (const float*)d_in[2];   // [N,G,M]
    float* out = (float*)d_out;

    k_prep <<<256, 256>>>(emb);
    k_gemm <<<dim3(M / BN, N_TOK / BM, G), 256>>>(x, emb);
    k_rows <<<dim3(N_TOK / ROWS, G), 256>>>(x, emb, gu, out);
    k_final<<<G, 256>>>(out);
}

// round 12
// speedup vs baseline: 1.0531x; 1.0002x over previous
#include <cuda_runtime.h>
#include <math.h>

// Problem constants
#define N_TOK 16384          // B*T
#define G     2
#define M     1024
#define D     256
#define GD    512            // G*D
#define GM    2048           // G*M

// Output layout (concatenated, float32):
//   quantized [8388608], code_perplexity [2], prob_perplexity [2],
//   quantization_inds [32768], commitment_loss [1]
#define OFF_Q    0
#define OFF_CODE 8388608
#define OFF_PROB 8388610
#define OFF_IND  8388612
#define OFF_LOSS 8421380

// -------- device scratch (static globals: no runtime allocation) --------
__device__ float  g_logits[33554432];   // [N_TOK, G, M] = 134 MB
__device__ float  g_sqe[GM];
__device__ float  g_avgprob[GM];
__device__ float  g_hardcnt[GM];
__device__ double g_commit;

// -------- packed f32x2 helpers (FFMA2: 2x fp32 FMA throughput) --------
__device__ __forceinline__ unsigned long long pk2(float lo, float hi) {
    unsigned long long r;
    asm("mov.b64 %0, {%1,%2};" : "=l"(r) : "f"(lo), "f"(hi));
    return r;
}
__device__ __forceinline__ void upk2(unsigned long long v, float& lo, float& hi) {
    asm("mov.b64 {%0,%1}, %2;" : "=f"(lo), "=f"(hi) : "l"(v));
}
__device__ __forceinline__ void fma2(unsigned long long& acc,
                                     unsigned long long a, unsigned long long b) {
    asm("fma.rn.f32x2 %0, %1, %2, %0;" : "+l"(acc) : "l"(a), "l"(b));
}

// ======================================================================
// K0: sq_e[g,m] = sum_d e^2 ; zero accumulators
// grid 256 blocks x 256 threads : one warp per (g,m) row
// ======================================================================
__global__ void k_prep(const float* __restrict__ emb) {
    int row  = blockIdx.x * 8 + (threadIdx.x >> 5);
    int lane = threadIdx.x & 31;
    if (row < GM) {
        const float* e = emb + (size_t)row * D;
        float s = 0.f;
        #pragma unroll
        for (int d = lane; d < D; d += 32) { float v = e[d]; s = fmaf(v, v, s); }
        #pragma unroll
        for (int o = 16; o > 0; o >>= 1) s += __shfl_xor_sync(0xffffffffu, s, o);
        if (lane == 0) {
            g_sqe[row]     = s;
            g_avgprob[row] = 0.f;
            g_hardcnt[row] = 0.f;
        }
    }
    if (blockIdx.x == 0 && threadIdx.x == 0) g_commit = 0.0;
}

// ======================================================================
// K1: L[n,g,m] = 2 * (x[n,g,:] . e[g,m,:]) - sq_e[g,m]
// fp32 tiled GEMM, 128x128 block tile, BK=16, 8x8 microtile, FFMA2
// grid (M/128, N/128, G) x 256 threads
// ======================================================================
#define BM 128
#define BN 128
#define BK 16

__global__ void __launch_bounds__(256) k_gemm(const float* __restrict__ x,
                                              const float* __restrict__ emb) {
    __shared__ float As[BK][BM];
    __shared__ float Bs[BK][BN];

    int g  = blockIdx.z;
    int m0 = blockIdx.x * BN;
    int n0 = blockIdx.y * BM;
    const float* A = x   + (size_t)g * D;        // row n: A[n*GD + d]
    const float* B = emb + (size_t)g * M * D;    // row m: B[m*D + d]

    int tid  = threadIdx.x;
    int tx   = tid & 15;          // 16 col-groups of 8
    int ty   = tid >> 4;          // 16 row-groups of 8
    int lrow = tid >> 2;          // 0..63
    int lcol = (tid & 3) << 2;    // 0,4,8,12

    unsigned long long acc[8][4];
    #pragma unroll
    for (int i = 0; i < 8; i++)
        #pragma unroll
        for (int j = 0; j < 4; j++) acc[i][j] = 0ULL;

    for (int k0 = 0; k0 < D; k0 += BK) {
        #pragma unroll
        for (int r = 0; r < 2; r++) {
            int row = lrow + r * 64;
            float4 va = *(const float4*)(A + (size_t)(n0 + row) * GD + k0 + lcol);
            As[lcol + 0][row] = va.x; As[lcol + 1][row] = va.y;
            As[lcol + 2][row] = va.z; As[lcol + 3][row] = va.w;
            float4 vb = *(const float4*)(B + (size_t)(m0 + row) * D + k0 + lcol);
            Bs[lcol + 0][row] = vb.x; Bs[lcol + 1][row] = vb.y;
            Bs[lcol + 2][row] = vb.z; Bs[lcol + 3][row] = vb.w;
        }
        __syncthreads();
        #pragma unroll
        for (int k = 0; k < BK; k++) {
            float4 a0 = *(const float4*)&As[k][ty * 8];
            float4 a1 = *(const float4*)&As[k][ty * 8 + 4];
            float4 b0 = *(const float4*)&Bs[k][tx * 8];
            float4 b1 = *(const float4*)&Bs[k][tx * 8 + 4];
            unsigned long long bb[4] = { pk2(b0.x, b0.y), pk2(b0.z, b0.w),
                                         pk2(b1.x, b1.y), pk2(b1.z, b1.w) };
            float av[8] = {a0.x, a0.y, a0.z, a0.w, a1.x, a1.y, a1.z, a1.w};
            #pragma unroll
            for (int i = 0; i < 8; i++) {
                unsigned long long aa = pk2(av[i], av[i]);
                #pragma unroll
                for (int j = 0; j < 4; j++) fma2(acc[i][j], aa, bb[j]);
            }
        }
        __syncthreads();
    }

    // epilogue: L = 2*cross - sq_e
    float sq[8];
    #pragma unroll
    for (int j = 0; j < 8; j++) sq[j] = g_sqe[g * M + m0 + tx * 8 + j];
    #pragma unroll
    for (int i = 0; i < 8; i++) {
        int n = n0 + ty * 8 + i;
        float* Lrow = g_logits + ((size_t)n * G + g) * M + m0 + tx * 8;
        #pragma unroll
        for (int j = 0; j < 4; j++) {
            float f0, f1; upk2(acc[i][j], f0, f1);
            float2 o;
            o.x = 2.0f * f0 - sq[2 * j];
            o.y = 2.0f * f1 - sq[2 * j + 1];
            *(float2*)(Lrow + 2 * j) = o;
        }
    }
}

// ======================================================================
// K2: per-row fused epilogue. 16 rows per block, 256 threads.
//  - hard argmax (first-occurrence ties)     -> hard counts
//  - gumbel argmax of L + (-log(-log(u)))    -> inds, gather, commit loss
//  - softmax over row                        -> avg_probs accumulation
// grid (N/16, G) x 256
// ======================================================================
#define ROWS 16

__global__ void __launch_bounds__(256) k_rows(const float* __restrict__ x,
                                              const float* __restrict__ emb,
                                              const float* __restrict__ gu,
                                              float* __restrict__ out) {
    int g    = blockIdx.y;
    int n0   = blockIdx.x * ROWS;
    int tid  = threadIdx.x;
    int lane = tid & 31, wid = tid >> 5;

    __shared__ float svL[8]; __shared__ int siL[8];
    __shared__ float svG[8]; __shared__ int siG[8];
    __shared__ float sLmax;  __shared__ int sLidx; __shared__ int sGidx;
    __shared__ float sZ;

    float accP[4]  = {0.f, 0.f, 0.f, 0.f};
    float hardC[4] = {0.f, 0.f, 0.f, 0.f};
    float commitLocal = 0.f;

    for (int r = 0; r < ROWS; r++) {
        int n = n0 + r;
        const float* Lrow = g_logits + ((size_t)n * G + g) * M;
        const float* Urow = gu       + ((size_t)n * G + g) * M;

        float Lv[4];
        float lmax = -3.4e38f; int lIdx = 0;
        float gmax = -3.4e38f; int gIdx = 0;
        #pragma unroll
        for (int j = 0; j < 4; j++) {
            int m   = tid + j * 256;            // ascending m within thread
            float L = Lrow[m];
            float u = Urow[m];
            // precise logf: -log(u) can be ~1e-6 when u -> 1; __logf would
            // destroy relative accuracy and flip argmaxes
            float noise = -logf(-logf(u));
            float gv = L + noise;
            Lv[j] = L;
            if (L  > lmax) { lmax = L;  lIdx = m; }   // strict > keeps first
            if (gv > gmax) { gmax = gv; gIdx = m; }
        }
        // warp argmax reductions (tie-break: smaller index)
        #pragma unroll
        for (int o = 16; o > 0; o >>= 1) {
            float v2 = __shfl_xor_sync(0xffffffffu, lmax, o);
            int   i2 = __shfl_xor_sync(0xffffffffu, lIdx, o);
            if (v2 > lmax || (v2 == lmax && i2 < lIdx)) { lmax = v2; lIdx = i2; }
            float v3 = __shfl_xor_sync(0xffffffffu, gmax, o);
            int   i3 = __shfl_xor_sync(0xffffffffu, gIdx, o);
            if (v3 > gmax || (v3 == gmax && i3 < gIdx)) { gmax = v3; gIdx = i3; }
        }
        if (lane == 0) { svL[wid] = lmax; siL[wid] = lIdx;
                         svG[wid] = gmax; siG[wid] = gIdx; }
        __syncthreads();
        if (tid == 0) {
            float lm = svL[0]; int li = siL[0];
            float gm = svG[0]; int gi = siG[0];
            #pragma unroll
            for (int w = 1; w < 8; w++) {
                if (svL[w] > lm || (svL[w] == lm && siL[w] < li)) { lm = svL[w]; li = siL[w]; }
                if (svG[w] > gm || (svG[w] == gm && siG[w] < gi)) { gm = svG[w]; gi = siG[w]; }
            }
            sLmax = lm; sLidx = li; sGidx = gi;
        }
        __syncthreads();
        float rowMax = sLmax;
        int   hIdx   = sLidx;
        int   qIdx   = sGidx;

        // softmax partition sum
        float e[4];
        float ez = 0.f;
        #pragma unroll
        for (int j = 0; j < 4; j++) { e[j] = __expf(Lv[j] - rowMax); ez += e[j]; }
        #pragma unroll
        for (int o = 16; o > 0; o >>= 1) ez += __shfl_xor_sync(0xffffffffu, ez, o);
        if (lane == 0) svL[wid] = ez;
        __syncthreads();
        if (tid == 0) {
            float z = 0.f;
            #pragma unroll
            for (int w = 0; w < 8; w++) z += svL[w];
            sZ = z;
        }
        __syncthreads();
        float invZ = 1.0f / sZ;
        #pragma unroll
        for (int j = 0; j < 4; j++) accP[j] += e[j] * invZ;

        // hard-assignment count (owner thread of hIdx)
        if (tid == (hIdx & 255)) hardC[hIdx >> 8] += 1.0f;

        // gumbel index output + gather + commitment partial
        if (tid == 0) out[OFF_IND + n * G + g] = (float)qIdx;
        const float* er = emb + ((size_t)g * M + qIdx) * D;
        float q  = er[tid];
        size_t xo = (size_t)n * GD + (size_t)g * D + tid;
        out[OFF_Q + xo] = q;
        float dd = x[xo] - q;
        commitLocal = fmaf(dd, dd, commitLocal);
    }

    // flush per-block accumulators (2M atomics total vs 33.5M naive)
    #pragma unroll
    for (int j = 0; j < 4; j++) {
        atomicAdd(&g_avgprob[g * M + tid + j * 256], accP[j]);
        if (hardC[j] != 0.f) atomicAdd(&g_hardcnt[g * M + tid + j * 256], hardC[j]);
    }
    // commitment loss block reduce
    #pragma unroll
    for (int o = 16; o > 0; o >>= 1)
        commitLocal += __shfl_xor_sync(0xffffffffu, commitLocal, o);
    __syncthreads();
    if (lane == 0) svL[wid] = commitLocal;
    __syncthreads();
    if (tid == 0) {
        float s = 0.f;
        #pragma unroll
        for (int w = 0; w < 8; w++) s += svL[w];
        atomicAdd(&g_commit, (double)s);
    }
}

// ======================================================================
// K3: perplexities + loss. grid (G) x 256
// ======================================================================
__global__ void k_final(float* __restrict__ out) {
    int g = blockIdx.x;
    int tid = threadIdx.x;
    __shared__ float s1[8], s2[8];
    float c = 0.f, p = 0.f;
    for (int m = tid; m < M; m += 256) {
        float hp = g_hardcnt[g * M + m] * (1.0f / N_TOK);
        float ap = g_avgprob[g * M + m] * (1.0f / N_TOK);
        c -= hp * log2f(hp + 1e-10f);
        p -= ap * log2f(ap + 1e-10f);
    }
    #pragma unroll
    for (int o = 16; o > 0; o >>= 1) {
        c += __shfl_xor_sync(0xffffffffu, c, o);
        p += __shfl_xor_sync(0xffffffffu, p, o);
    }
    int lane = tid & 31, w = tid >> 5;
    if (lane == 0) { s1[w] = c; s2[w] = p; }
    __syncthreads();
    if (tid == 0) {
        float cc = 0.f, pp = 0.f;
        #pragma unroll
        for (int i = 0; i < 8; i++) { cc += s1[i]; pp += s2[i]; }
        out[OFF_CODE + g] = cc;
        out[OFF_PROB + g] = pp;
        if (g == 0) out[OFF_LOSS] = (float)(g_commit / 8388608.0);  // mean over B*T*G*D
    }
}

// ======================================================================
extern "C" void kernel_launch(void* const* d_in, const int* in_sizes, int n_in,
                              void* d_out, int out_size) {
    const float* x   = (const float*)d_in[0];   // [B,T,G*D]
    const float* emb = (const float*)d_in[1];   // [G,M,D]
    const float* gu  = (const float*)d_in[2];   // [N,G,M]
    float* out = (float*)d_out;

    k_prep <<<256, 256>>>(emb);
    k_gemm <<<dim3(M / BN, N_TOK / BM, G), 256>>>(x, emb);
    k_rows <<<dim3(N_TOK / ROWS, G), 256>>>(x, emb, gu, out);
    k_final<<<G, 256>>>(out);
}